// round 11
// baseline (speedup 1.0000x reference)
#include <cuda_runtime.h>
#include <cstdint>

// GaborLayer: out[p, c] = sin(x_p . W_c + b_c) * exp(-0.5 * ||x_p - mu_c||^2 * gamma_c)
// 262144 points x 256 channels, fp32 out.
//
// R10: sin moved OFF the MUFU pipe onto the FMA pipe as a packed f32x2 polynomial
// (magic-round range reduction by pi, parity sign from packed mantissa bits, deg-9
// odd Taylor on [-pi/2, pi/2]). ex2 stays on MUFU (1 MUFU/elem instead of 2).
// Persistent grid-stride single kernel (R5 structure, best measured total),
// 2 channels/thread, pre-splatted smem tiles, register prefetch, launch_bounds(256,5).
//
// exponent*log2e = a.x + ah*||x||^2 + cc,  a = g*mu, ah = -g/2, cc = ah*||mu||^2,
// g = gamma*log2e  -> one ex2.approx per element.

#define TP  64
#define NCH 256

typedef unsigned long long u64;

__device__ __forceinline__ u64 pack2(float lo, float hi) {
    u64 r; asm("mov.b64 %0, {%1, %2};" : "=l"(r) : "f"(lo), "f"(hi)); return r;
}
__device__ __forceinline__ void unpack2(float& lo, float& hi, u64 v) {
    asm("mov.b64 {%0, %1}, %2;" : "=f"(lo), "=f"(hi) : "l"(v));
}
__device__ __forceinline__ u64 fma2(u64 a, u64 b, u64 c) {
    u64 d; asm("fma.rn.f32x2 %0, %1, %2, %3;" : "=l"(d) : "l"(a), "l"(b), "l"(c)); return d;
}
__device__ __forceinline__ u64 add2(u64 a, u64 b) {
    u64 d; asm("add.rn.f32x2 %0, %1, %2;" : "=l"(d) : "l"(a), "l"(b)); return d;
}
__device__ __forceinline__ u64 mul2(u64 a, u64 b) {
    u64 d; asm("mul.rn.f32x2 %0, %1, %2;" : "=l"(d) : "l"(a), "l"(b)); return d;
}

__global__ __launch_bounds__(256, 5) void gabor_kernel(
    const float* __restrict__ x,
    const float* __restrict__ W,
    const float* __restrict__ b,
    const float* __restrict__ mu,
    const float* __restrict__ gamma,
    float* __restrict__ out,
    int ntiles)
{
    __shared__ float      raw[TP * 3];        // 768 B
    __shared__ ulonglong2 pts2[TP][2];        // [p][0]={x,x,y,y} [p][1]={z,z,w,w}

    const int tid = threadIdx.x;
    const int cg  = tid & 127;                // channel pair: channels 2cg, 2cg+1
    const int pl  = tid >> 7;                 // point lane 0..1

    // ---- per-thread constants for 2 channels, loaded ONCE per persistent block ----
    const float L2E = 1.4426950408889634f;
    const int c0 = 2 * cg, c1 = c0 + 1;
    const float m00 = mu[c0*3+0], m01 = mu[c0*3+1], m02 = mu[c0*3+2];
    const float m10 = mu[c1*3+0], m11 = mu[c1*3+1], m12 = mu[c1*3+2];
    const float g0 = gamma[c0] * L2E, g1 = gamma[c1] * L2E;

    const u64 wx = pack2(W[c0*3+0], W[c1*3+0]);
    const u64 wy = pack2(W[c0*3+1], W[c1*3+1]);
    const u64 wz = pack2(W[c0*3+2], W[c1*3+2]);
    const u64 bb = pack2(b[c0], b[c1]);
    const u64 ax = pack2(g0 * m00, g1 * m10);
    const u64 ay = pack2(g0 * m01, g1 * m11);
    const u64 az = pack2(g0 * m02, g1 * m12);
    const float ah0 = -0.5f * g0, ah1 = -0.5f * g1;
    const u64 ah = pack2(ah0, ah1);
    const u64 cc = pack2(ah0 * (m00*m00 + m01*m01 + m02*m02),
                         ah1 * (m10*m10 + m11*m11 + m12*m12));

    // ---- sin-poly constants (compile-time floats, packed once) ----
    const float MAGICF = 12582912.0f;                  // 1.5 * 2^23
    const u64 INVPI2 = pack2(0.31830988618f,  0.31830988618f);
    const u64 MAGIC2 = pack2(MAGICF,          MAGICF);
    const u64 NMAGI2 = pack2(-MAGICF,        -MAGICF);
    const u64 NEGPI2 = pack2(-3.14159265359f, -3.14159265359f);
    const u64 S1 = pack2(-1.66666667e-1f, -1.66666667e-1f);
    const u64 S2 = pack2( 8.33333333e-3f,  8.33333333e-3f);
    const u64 S3 = pack2(-1.98412698e-4f, -1.98412698e-4f);
    const u64 S4 = pack2( 2.75573192e-6f,  2.75573192e-6f);

    const int pbase = pl * (TP / 2);
    const int g     = gridDim.x;

    float4 pre;
    {
        const int t0i = blockIdx.x;
        if (t0i < ntiles && tid < TP * 3 / 4)
            pre = ((const float4*)(x + (size_t)t0i * TP * 3))[tid];
    }

    for (int tile = blockIdx.x; tile < ntiles; tile += g) {
        // stage prefetched coords (raw hazard vs pack readers closed by prev sync2)
        if (tid < TP * 3 / 4) ((float4*)raw)[tid] = pre;
        __syncthreads();                       // raw visible to packers

        if (tid < TP) {
            const float v0 = raw[tid*3+0], v1 = raw[tid*3+1], v2 = raw[tid*3+2];
            const float w  = v0*v0 + v1*v1 + v2*v2;
            float4* d = (float4*)pts2[tid];
            d[0] = make_float4(v0, v0, v1, v1);
            d[1] = make_float4(v2, v2, w,  w);
        }
        if (tile + g < ntiles && tid < TP * 3 / 4)   // prefetch next tile (overlaps compute)
            pre = ((const float4*)(x + (size_t)(tile + g) * TP * 3))[tid];
        __syncthreads();                       // pts2 visible

        float* o = out + (size_t)(tile * TP + pbase) * NCH + c0;

        #pragma unroll 8
        for (int i = 0; i < TP / 2; i++) {
            const ulonglong2 A = pts2[pbase + i][0];   // {x,x}, {y,y}  (LDS.128 broadcast)
            const ulonglong2 B = pts2[pbase + i][1];   // {z,z}, {w,w}

            // lin = W.x + b
            u64 l = fma2(wz, B.x, bb);
            l = fma2(wy, A.y, l);
            l = fma2(wx, A.x, l);

            // e = a.x + ah*||x||^2 + cc   (log2-scaled exponent)
            u64 e = fma2(ah, B.y, cc);
            e = fma2(az, B.x, e);
            e = fma2(ay, A.y, e);
            e = fma2(ax, A.x, e);

            // ---- packed sin(l): reduce by pi, parity sign, deg-9 odd poly ----
            const u64 t  = fma2(l, INVPI2, MAGIC2);    // n + magic (per lane)
            const u64 sg = (t & 0x0000000100000001ULL) << 31;  // parity -> sign bits
            const u64 n  = add2(t, NMAGI2);            // n as float
            const u64 r  = fma2(n, NEGPI2, l);         // r = l - n*pi, |r| <= pi/2
            const u64 r2 = mul2(r, r);
            u64 p = fma2(r2, S4, S3);
            p = fma2(r2, p, S2);
            p = fma2(r2, p, S1);
            p = mul2(p, r2);
            const u64 s = fma2(p, r, r);               // sin(r) (unsigned by parity)

            // ---- exp via MUFU ex2 (1 per element) ----
            float e0, e1;
            unpack2(e0, e1, e);
            float t0, t1;
            asm("ex2.approx.f32 %0, %1;" : "=f"(t0) : "f"(e0));
            asm("ex2.approx.f32 %0, %1;" : "=f"(t1) : "f"(e1));
            const u64 ex = pack2(t0, t1);

            u64 res = mul2(s, ex) ^ sg;                // apply parity sign at the end

            asm volatile("st.global.b64 [%0], %1;"
                         :: "l"(o + (size_t)i * NCH), "l"(res) : "memory");
        }
    }
}

extern "C" void kernel_launch(void* const* d_in, const int* in_sizes, int n_in,
                              void* d_out, int out_size)
{
    const float* x     = (const float*)d_in[0];  // (4, 65536, 3)
    const float* W     = (const float*)d_in[1];  // (256, 3)
    const float* b     = (const float*)d_in[2];  // (256,)
    const float* mu    = (const float*)d_in[3];  // (256, 3)
    const float* gamma = (const float*)d_in[4];  // (256,)
    float* out = (float*)d_out;                  // (4, 65536, 256)

    const int npts   = in_sizes[0] / 3;          // 262144
    const int ntiles = npts / TP;                // 4096

    static int nsm = 0;                          // device attr cache (no device mem)
    if (nsm == 0) {
        cudaDeviceGetAttribute(&nsm, cudaDevAttrMultiProcessorCount, 0);
        if (nsm <= 0) nsm = 148;
    }
    int grid = nsm * 5;
    if (grid > ntiles) grid = ntiles;

    gabor_kernel<<<grid, NCH>>>(x, W, b, mu, gamma, out, ntiles);
}

// round 12
// speedup vs baseline: 1.2533x; 1.2533x over previous
#include <cuda_runtime.h>
#include <cstdint>

// GaborLayer: out[p, c] = sin(x_p . W_c + b_c) * exp(-0.5 * ||x_p - mu_c||^2 * gamma_c)
// 262144 points x 256 channels, fp32 out.
//
// R11: champion config (R5) consolidated. Persistent grid-stride single kernel
// (grid = SMs*6), MUFU __sinf + ex2.approx (poly-sin regressed: latency chain +
// occupancy loss), 2 channels/thread, f32x2 FFMA2 lin/exponent, pre-splatted smem
// tiles. Delta vs R5: TP=128 (half the sync boundaries), register prefetch of the
// next tile's coords, plain v2 stores.
//
// exponent*log2e = a.x + ah*||x||^2 + cc,  a = g*mu, ah = -g/2, cc = ah*||mu||^2,
// g = gamma*log2e  -> one ex2.approx per element.

#define TP  128
#define NCH 256

typedef unsigned long long u64;

__device__ __forceinline__ u64 pack2(float lo, float hi) {
    u64 r; asm("mov.b64 %0, {%1, %2};" : "=l"(r) : "f"(lo), "f"(hi)); return r;
}
__device__ __forceinline__ void unpack2(float& lo, float& hi, u64 v) {
    asm("mov.b64 {%0, %1}, %2;" : "=f"(lo), "=f"(hi) : "l"(v));
}
__device__ __forceinline__ u64 fma2(u64 a, u64 b, u64 c) {
    u64 d; asm("fma.rn.f32x2 %0, %1, %2, %3;" : "=l"(d) : "l"(a), "l"(b), "l"(c)); return d;
}

__global__ __launch_bounds__(256, 6) void gabor_kernel(
    const float* __restrict__ x,
    const float* __restrict__ W,
    const float* __restrict__ b,
    const float* __restrict__ mu,
    const float* __restrict__ gamma,
    float* __restrict__ out,
    int ntiles)
{
    __shared__ float      raw[TP * 3];        // 1536 B
    __shared__ ulonglong2 pts2[TP][2];        // [p][0]={x,x,y,y} [p][1]={z,z,w,w}, 4 KB

    const int tid = threadIdx.x;
    const int cg  = tid & 127;                // channel pair: channels 2cg, 2cg+1
    const int pl  = tid >> 7;                 // point lane 0..1

    // ---- per-thread constants for 2 channels, loaded ONCE per persistent block ----
    const float L2E = 1.4426950408889634f;
    const int c0 = 2 * cg, c1 = c0 + 1;
    const float m00 = mu[c0*3+0], m01 = mu[c0*3+1], m02 = mu[c0*3+2];
    const float m10 = mu[c1*3+0], m11 = mu[c1*3+1], m12 = mu[c1*3+2];
    const float g0 = gamma[c0] * L2E, g1 = gamma[c1] * L2E;

    const u64 wx = pack2(W[c0*3+0], W[c1*3+0]);
    const u64 wy = pack2(W[c0*3+1], W[c1*3+1]);
    const u64 wz = pack2(W[c0*3+2], W[c1*3+2]);
    const u64 bb = pack2(b[c0], b[c1]);
    const u64 ax = pack2(g0 * m00, g1 * m10);
    const u64 ay = pack2(g0 * m01, g1 * m11);
    const u64 az = pack2(g0 * m02, g1 * m12);
    const float ah0 = -0.5f * g0, ah1 = -0.5f * g1;
    const u64 ah = pack2(ah0, ah1);
    const u64 cc = pack2(ah0 * (m00*m00 + m01*m01 + m02*m02),
                         ah1 * (m10*m10 + m11*m11 + m12*m12));

    const int pbase = pl * (TP / 2);
    const int g     = gridDim.x;

    float4 pre;
    if (blockIdx.x < ntiles && tid < TP * 3 / 4)
        pre = ((const float4*)(x + (size_t)blockIdx.x * TP * 3))[tid];

    for (int tile = blockIdx.x; tile < ntiles; tile += g) {
        // stage prefetched coords (raw hazard vs pack readers closed by prev sync2)
        if (tid < TP * 3 / 4) ((float4*)raw)[tid] = pre;
        __syncthreads();                       // raw visible to packers

        if (tid < TP) {
            const float v0 = raw[tid*3+0], v1 = raw[tid*3+1], v2 = raw[tid*3+2];
            const float w  = v0*v0 + v1*v1 + v2*v2;
            float4* d = (float4*)pts2[tid];
            d[0] = make_float4(v0, v0, v1, v1);
            d[1] = make_float4(v2, v2, w,  w);
        }
        if (tile + g < ntiles && tid < TP * 3 / 4)   // prefetch next tile (overlaps compute)
            pre = ((const float4*)(x + (size_t)(tile + g) * TP * 3))[tid];
        __syncthreads();                       // pts2 visible

        float* o = out + (size_t)(tile * TP + pbase) * NCH + c0;

        #pragma unroll 8
        for (int i = 0; i < TP / 2; i++) {
            const ulonglong2 A = pts2[pbase + i][0];   // {x,x}, {y,y}  (LDS.128 broadcast)
            const ulonglong2 B = pts2[pbase + i][1];   // {z,z}, {w,w}

            // lin = W.x + b
            u64 l = fma2(wz, B.x, bb);
            l = fma2(wy, A.y, l);
            l = fma2(wx, A.x, l);

            // e = a.x + ah*||x||^2 + cc   (log2-scaled exponent)
            u64 e = fma2(ah, B.y, cc);
            e = fma2(az, B.x, e);
            e = fma2(ay, A.y, e);
            e = fma2(ax, A.x, e);

            float l0, l1, e0, e1;
            unpack2(l0, l1, l);
            unpack2(e0, e1, e);

            float t0, t1;
            asm("ex2.approx.f32 %0, %1;" : "=f"(t0) : "f"(e0));
            asm("ex2.approx.f32 %0, %1;" : "=f"(t1) : "f"(e1));

            const float r0 = __sinf(l0) * t0;
            const float r1 = __sinf(l1) * t1;
            asm volatile("st.global.v2.f32 [%0], {%1, %2};"
                         :: "l"(o + (size_t)i * NCH), "f"(r0), "f"(r1) : "memory");
        }
    }
}

extern "C" void kernel_launch(void* const* d_in, const int* in_sizes, int n_in,
                              void* d_out, int out_size)
{
    const float* x     = (const float*)d_in[0];  // (4, 65536, 3)
    const float* W     = (const float*)d_in[1];  // (256, 3)
    const float* b     = (const float*)d_in[2];  // (256,)
    const float* mu    = (const float*)d_in[3];  // (256, 3)
    const float* gamma = (const float*)d_in[4];  // (256,)
    float* out = (float*)d_out;                  // (4, 65536, 256)

    const int npts   = in_sizes[0] / 3;          // 262144
    const int ntiles = npts / TP;                // 2048

    static int nsm = 0;                          // device attr cache (no device mem)
    if (nsm == 0) {
        cudaDeviceGetAttribute(&nsm, cudaDevAttrMultiProcessorCount, 0);
        if (nsm <= 0) nsm = 148;
    }
    int grid = nsm * 6;
    if (grid > ntiles) grid = ntiles;

    gabor_kernel<<<grid, NCH>>>(x, W, b, mu, gamma, out, ntiles);
}